// round 1
// baseline (speedup 1.0000x reference)
#include <cuda_runtime.h>
#include <math.h>

#define BSZ 1024

// ---------------- scratch (device globals; no allocations allowed) ----------------
__device__ float g_X1[BSZ*128];     // [t, x_gene] grn input
__device__ float g_XB[BSZ*129];     // [t, x] b-net input
__device__ float g_h1[BSZ*1024];
__device__ float g_d1[BSZ*1024];
__device__ float g_h2[BSZ*960];
__device__ float g_d2[BSZ*960];
__device__ float g_h3[BSZ*896];
__device__ float g_d3[BSZ*896];
__device__ float g_e1[BSZ*512];
__device__ float g_e2[BSZ*448];
__device__ float g_gv[BSZ];
__device__ float g_tr[BSZ];

// ---------------- prep: build inputs, zero trace accumulators ----------------
__global__ void prep_kernel(const float* __restrict__ pt, const float* __restrict__ x)
{
    int b = blockIdx.x;
    int t = threadIdx.x;
    float tv = pt[0];
    if (t == 0){ g_X1[b*128] = tv; g_XB[b*129] = tv; g_tr[b] = 0.f; }
    for (int c = t; c < 128; c += blockDim.x){
        float xv = x[b*128 + c];
        if (c < 127) g_X1[b*128 + 1 + c] = xv;
        g_XB[b*129 + 1 + c] = xv;
    }
}

// ---------------- generic fp32 GEMM: C = act(A @ W + bias), M=1024 ----------------
// A: [1024 x K] (lda), W: [K x N] row-major, tile 64x64, BK=16, 256 threads (4x4/thread)
template<bool TANH>
__global__ __launch_bounds__(256)
void fwd_gemm(const float* __restrict__ A, int lda,
              const float* __restrict__ W,
              const float* __restrict__ bias,
              float* __restrict__ H, float* __restrict__ Dm,
              int N, int K)
{
    __shared__ float sA[16*65];   // [k][m] transposed, padded
    __shared__ float sB[16*64];   // [k][n]
    int n0 = blockIdx.x * 64;
    int m0 = blockIdx.y * 64;
    int tid = threadIdx.x;
    int tx = tid & 15, ty = tid >> 4;
    float acc[4][4] = {};
    for (int k0 = 0; k0 < K; k0 += 16){
        #pragma unroll
        for (int e = 0; e < 4; e++){
            int id = tid + e*256;
            int m = id >> 4, k = id & 15;
            sA[k*65 + m] = (k0 + k < K) ? A[(m0+m)*lda + k0 + k] : 0.f;
        }
        #pragma unroll
        for (int e = 0; e < 4; e++){
            int id = tid + e*256;
            int kb = id >> 6, n = id & 63;
            sB[kb*64 + n] = (k0 + kb < K) ? W[(k0+kb)*N + n0 + n] : 0.f;
        }
        __syncthreads();
        #pragma unroll
        for (int kk = 0; kk < 16; kk++){
            float a[4], bb[4];
            #pragma unroll
            for (int r = 0; r < 4; r++) a[r] = sA[kk*65 + ty*4 + r];
            #pragma unroll
            for (int c = 0; c < 4; c++) bb[c] = sB[kk*64 + tx*4 + c];
            #pragma unroll
            for (int r = 0; r < 4; r++)
                #pragma unroll
                for (int c = 0; c < 4; c++)
                    acc[r][c] += a[r]*bb[c];
        }
        __syncthreads();
    }
    #pragma unroll
    for (int r = 0; r < 4; r++){
        int m = m0 + ty*4 + r;
        #pragma unroll
        for (int c = 0; c < 4; c++){
            int n = n0 + tx*4 + c;
            float v = acc[r][c] + bias[n];
            if (TANH){
                float h = tanhf(v);
                H[m*N + n] = h;
                if (Dm) Dm[m*N + n] = 1.f - h*h;
            } else {
                H[m*N + n] = v;
            }
        }
    }
}

// ---------------- b-net head: g[b] = e2[b] . bdw + bdb ----------------
__global__ void bnet_head(const float* __restrict__ bdw, const float* __restrict__ bdb,
                          float* __restrict__ out_g)
{
    int b = blockIdx.x;
    int t = threadIdx.x; // 128
    float s = 0.f;
    for (int k = t; k < 448; k += 128) s += g_e2[b*448 + k] * bdw[k];
    #pragma unroll
    for (int off = 16; off > 0; off >>= 1) s += __shfl_xor_sync(0xffffffffu, s, off);
    __shared__ float sw[4];
    if ((t & 31) == 0) sw[t >> 5] = s;
    __syncthreads();
    if (t == 0){
        float g = sw[0] + sw[1] + sw[2] + sw[3] + bdb[0];
        g_gv[b] = g;
        out_g[b] = g;
    }
}

// ---------------- Jacobian trace: fused per-sample meet-in-the-middle ----------------
// CTA = (sample b, k-tile kt of 64 cols of the 960-dim hidden-2 index).
// GEMM1: L[i,k]  = sum_j W0[i+1,j]*d1[j]*W1[j,kt+k]      (128x64, K=1024)
// GEMM2: R[k,i]  = sum_l W2[kt+k,l]*d3[l]*Wd[l,i]         (64x128, K=896)
// partial tr    += sum_{i,k} L[i,k]*d2[kt+k]*R[k,i]
#define TKJ 64
__global__ __launch_bounds__(256)
void jac_kernel(const float* __restrict__ gw0,
                const float* __restrict__ gw1,
                const float* __restrict__ gw2,
                const float* __restrict__ gdw)
{
    __shared__ __align__(16) float sbuf[128*17 + 16*64];  // gemm1: A[128][17] + B[16][64]; gemm2 aliases
    __shared__ float sLt[128*65];                          // L * d2, [i][k], padded
    __shared__ float sd2[TKJ];
    __shared__ float swarp[8];
    int b  = blockIdx.x;
    int kt = blockIdx.y * TKJ;
    int tid = threadIdx.x;

    if (tid < TKJ) sd2[tid] = g_d2[b*960 + kt + tid];

    // ---- GEMM1 ----
    {
        float* sA = sbuf;             // [128][17]  raw W0 rows (i -> W0 row i+1; i=127 -> 0)
        float* sB = sbuf + 128*17;    // [16][64]   W1 rows scaled by d1[j]
        int tx = tid & 15, ty = tid >> 4;           // thread tile: rows i=ty*8..+7, cols k=tx*4..+3
        float acc[8][4] = {};
        int ai  = tid >> 1;           // 0..127
        int ac0 = (tid & 1) * 8;
        int bj  = tid >> 4;           // 0..15
        int bk4 = (tid & 15) * 4;
        for (int j0 = 0; j0 < 1024; j0 += 16){
            #pragma unroll
            for (int e = 0; e < 8; e++)
                sA[ai*17 + ac0 + e] = (ai < 127) ? gw0[(ai+1)*1024 + j0 + ac0 + e] : 0.f;
            {
                float d1v = g_d1[b*1024 + j0 + bj];
                float4 v = *(const float4*)&gw1[(j0+bj)*960 + kt + bk4];
                float* dst = &sB[bj*64 + bk4];
                dst[0]=v.x*d1v; dst[1]=v.y*d1v; dst[2]=v.z*d1v; dst[3]=v.w*d1v;
            }
            __syncthreads();
            #pragma unroll
            for (int jj = 0; jj < 16; jj++){
                float a[8];
                #pragma unroll
                for (int r = 0; r < 8; r++) a[r] = sA[(ty*8+r)*17 + jj];
                float4 b4 = *(const float4*)&sB[jj*64 + tx*4];
                #pragma unroll
                for (int r = 0; r < 8; r++){
                    acc[r][0] += a[r]*b4.x; acc[r][1] += a[r]*b4.y;
                    acc[r][2] += a[r]*b4.z; acc[r][3] += a[r]*b4.w;
                }
            }
            __syncthreads();
        }
        #pragma unroll
        for (int r = 0; r < 8; r++)
            #pragma unroll
            for (int c = 0; c < 4; c++)
                sLt[(ty*8+r)*65 + tx*4 + c] = acc[r][c] * sd2[tx*4 + c];
        __syncthreads();
    }

    // ---- GEMM2 + fused reduction ----
    float partial = 0.f;
    {
        float* sA2 = sbuf;            // [64][17]  W2 tile rows (k)
        float* sB2 = sbuf + 64*17;    // [16][128] Wd rows scaled by d3[l]
        int tx2 = tid & 15;           // i = tx2*8..+7
        int ty2 = tid >> 4;           // k = ty2*4..+3
        float acc2[4][8] = {};
        int ak  = tid >> 2;           // 0..63
        int ac0 = (tid & 3) * 4;
        int bl  = tid >> 4;           // 0..15
        int bi0 = (tid & 15) * 8;
        for (int l0 = 0; l0 < 896; l0 += 16){
            {
                float4 v = *(const float4*)&gw2[(kt+ak)*896 + l0 + ac0];
                float* dst = &sA2[ak*17 + ac0];
                dst[0]=v.x; dst[1]=v.y; dst[2]=v.z; dst[3]=v.w;
            }
            {
                float d3v = g_d3[b*896 + l0 + bl];
                const float4* src = (const float4*)&gdw[(l0+bl)*128 + bi0];
                float4 v0 = src[0], v1 = src[1];
                float* dst = &sB2[bl*128 + bi0];
                dst[0]=v0.x*d3v; dst[1]=v0.y*d3v; dst[2]=v0.z*d3v; dst[3]=v0.w*d3v;
                dst[4]=v1.x*d3v; dst[5]=v1.y*d3v; dst[6]=v1.z*d3v; dst[7]=v1.w*d3v;
            }
            __syncthreads();
            #pragma unroll
            for (int ll = 0; ll < 16; ll++){
                float a[4];
                #pragma unroll
                for (int r = 0; r < 4; r++) a[r] = sA2[(ty2*4+r)*17 + ll];
                float4 v0 = *(const float4*)&sB2[ll*128 + tx2*8];
                float4 v1 = *(const float4*)&sB2[ll*128 + tx2*8 + 4];
                #pragma unroll
                for (int r = 0; r < 4; r++){
                    acc2[r][0] += a[r]*v0.x; acc2[r][1] += a[r]*v0.y;
                    acc2[r][2] += a[r]*v0.z; acc2[r][3] += a[r]*v0.w;
                    acc2[r][4] += a[r]*v1.x; acc2[r][5] += a[r]*v1.y;
                    acc2[r][6] += a[r]*v1.z; acc2[r][7] += a[r]*v1.w;
                }
            }
            __syncthreads();
        }
        // tr partial: acc2[r][c] is R[k=ty2*4+r][i=tx2*8+c]; pair with sLt[i][k] (d2 folded).
        // Row i=127 of L is exactly zero, so the out-of-range trace term vanishes.
        #pragma unroll
        for (int r = 0; r < 4; r++)
            #pragma unroll
            for (int c = 0; c < 8; c++)
                partial += acc2[r][c] * sLt[(tx2*8 + c)*65 + ty2*4 + r];
    }
    #pragma unroll
    for (int off = 16; off > 0; off >>= 1)
        partial += __shfl_xor_sync(0xffffffffu, partial, off);
    if ((tid & 31) == 0) swarp[tid >> 5] = partial;
    __syncthreads();
    if (tid == 0){
        float s = 0.f;
        #pragma unroll
        for (int w = 0; w < 8; w++) s += swarp[w];
        atomicAdd(&g_tr[b], s);
    }
}

// ---------------- finalize: dp_dt = g - p * tr ----------------
__global__ void fin_kernel(const float* __restrict__ p, float* __restrict__ out_dp)
{
    int b = blockIdx.x * blockDim.x + threadIdx.x;
    if (b < BSZ) out_dp[b] = g_gv[b] - p[b] * g_tr[b];
}

// ---------------- launch ----------------
extern "C" void kernel_launch(void* const* d_in, const int* in_sizes, int n_in,
                              void* d_out, int out_size)
{
    const float* pt  = (const float*)d_in[0];
    const float* x   = (const float*)d_in[1];
    // d_in[2] = g_x (unused by reference)
    const float* p   = (const float*)d_in[3];
    const float* gw0 = (const float*)d_in[4];
    const float* gb0 = (const float*)d_in[5];
    const float* gw1 = (const float*)d_in[6];
    const float* gb1 = (const float*)d_in[7];
    const float* gw2 = (const float*)d_in[8];
    const float* gb2 = (const float*)d_in[9];
    const float* gdw = (const float*)d_in[10];
    const float* gdb = (const float*)d_in[11];
    const float* bw0 = (const float*)d_in[12];
    const float* bb0 = (const float*)d_in[13];
    const float* bw1 = (const float*)d_in[14];
    const float* bb1 = (const float*)d_in[15];
    const float* bdw = (const float*)d_in[16];
    const float* bdb = (const float*)d_in[17];
    float* out = (float*)d_out;

    float *pX1, *pXB, *ph1, *pd1, *ph2, *pd2, *ph3, *pd3, *pe1, *pe2;
    cudaGetSymbolAddress((void**)&pX1, g_X1);
    cudaGetSymbolAddress((void**)&pXB, g_XB);
    cudaGetSymbolAddress((void**)&ph1, g_h1);
    cudaGetSymbolAddress((void**)&pd1, g_d1);
    cudaGetSymbolAddress((void**)&ph2, g_h2);
    cudaGetSymbolAddress((void**)&pd2, g_d2);
    cudaGetSymbolAddress((void**)&ph3, g_h3);
    cudaGetSymbolAddress((void**)&pd3, g_d3);
    cudaGetSymbolAddress((void**)&pe1, g_e1);
    cudaGetSymbolAddress((void**)&pe2, g_e2);

    prep_kernel<<<BSZ, 256>>>(pt, x);
    // grn forward (stores h and d = 1 - h^2)
    fwd_gemm<true ><<<dim3(16, 16), 256>>>(pX1, 128,  gw0, gb0, ph1, pd1, 1024, 128);
    fwd_gemm<true ><<<dim3(15, 16), 256>>>(ph1, 1024, gw1, gb1, ph2, pd2, 960,  1024);
    fwd_gemm<true ><<<dim3(14, 16), 256>>>(ph2, 960,  gw2, gb2, ph3, pd3, 896,  960);
    fwd_gemm<false><<<dim3(2,  16), 256>>>(ph3, 896,  gdw, gdb, out, nullptr, 128, 896);
    // b-net forward
    fwd_gemm<true ><<<dim3(8,  16), 256>>>(pXB, 129,  bw0, bb0, pe1, nullptr, 512, 129);
    fwd_gemm<true ><<<dim3(7,  16), 256>>>(pe1, 512,  bw1, bb1, pe2, nullptr, 448, 512);
    bnet_head<<<BSZ, 128>>>(bdw, bdb, out + BSZ*128);
    // Jacobian trace (dominant cost)
    jac_kernel<<<dim3(BSZ, 15), 256>>>(gw0, gw1, gw2, gdw);
    fin_kernel<<<4, 256>>>(p, out + BSZ*128 + BSZ);
}